// round 6
// baseline (speedup 1.0000x reference)
#include <cuda_runtime.h>
#include <math.h>

#define CONF_TH 0.25f
#define NMS_TH  0.35f
#define FULL    0xffffffffu

static constexpr int N_IMG  = 64;
static constexpr int HW     = 1024;   // 32*32
static constexpr int NCH    = 85;
static constexpr int NCLS   = 80;
static constexpr int NTASK  = N_IMG * NCLS;   // 5120
static constexpr int SLOTS  = 32;

// static scratch (allowed: __device__ globals, no allocation; zero-initialized)
__device__ unsigned long long g_key  [N_IMG * HW];          // full keys (fallback path)
__device__ float4             g_box  [N_IMG * HW];          // decoded boxes by pixel
__device__ unsigned           g_cnt  [NTASK];               // per-(img,cls) candidate count
__device__ unsigned long long g_slots[NTASK * SLOTS];       // per-(img,cls) candidate keys

// ============================================================
// Kernel A: decode. grid = 128 (2 slices/image), block = 128.
// Each thread decodes 4 consecutive pixels with float4 loads.
// ============================================================
__global__ __launch_bounds__(128)
void decode_kernel(const float* __restrict__ in, float* __restrict__ out)
{
    const int n  = blockIdx.x >> 1;           // image
    const int s  = blockIdx.x & 1;            // slice
    const int p0 = s * 512 + threadIdx.x * 4; // first pixel (multiple of 4)

    const float4* base = (const float4*)(in + (size_t)n * NCH * HW) + (p0 >> 2);
    // channel c lives at base[c * 256]

    float4 pobj = base[0 * 256];
    float4 r0   = base[1 * 256];
    float4 r1   = base[2 * 256];
    float4 r2   = base[3 * 256];
    float4 r3   = base[4 * 256];

    // per-component argmax over 80 classes (first occurrence via strict >)
    float4 bv = make_float4(-INFINITY, -INFINITY, -INFINITY, -INFINITY);
    int4   bj = make_int4(0, 0, 0, 0);
    #pragma unroll 10
    for (int c = 0; c < NCLS; c++) {
        float4 v = base[(5 + c) * 256];
        if (v.x > bv.x) { bv.x = v.x; bj.x = c; }
        if (v.y > bv.y) { bv.y = v.y; bj.y = c; }
        if (v.z > bv.z) { bv.z = v.z; bj.z = c; }
        if (v.w > bv.w) { bv.w = v.w; bj.w = c; }
    }

    float sc[4]   = { pobj.x * bv.x, pobj.y * bv.y, pobj.z * bv.z, pobj.w * bv.w };
    float rr0[4]  = { r0.x, r0.y, r0.z, r0.w };
    float rr1[4]  = { r1.x, r1.y, r1.z, r1.w };
    float rr2[4]  = { r2.x, r2.y, r2.z, r2.w };
    float rr3[4]  = { r3.x, r3.y, r3.z, r3.w };
    int   cl[4]   = { bj.x, bj.y, bj.z, bj.w };

    float vals[24];
    unsigned long long keys[4];
    float4 boxes[4];
    bool   cands[4];

    #pragma unroll
    for (int l = 0; l < 4; l++) {
        int p = p0 + l;
        float gx = (float)(p & 31);
        float gy = (float)(p >> 5);
        float bcx = (tanhf(rr0[l]) + gx) * (1.0f / 32.0f);
        float bcy = (tanhf(rr1[l]) + gy) * (1.0f / 32.0f);
        float bw  = 1.0f / (1.0f + expf(-rr2[l]));
        float bh  = 1.0f / (1.0f + expf(-rr3[l]));
        float x1 = bcx - 0.5f * bw;
        float y1 = bcy - 0.5f * bh;
        float x2 = bcx + 0.5f * bw;
        float y2 = bcy + 0.5f * bh;

        vals[l * 6 + 0] = x1; vals[l * 6 + 1] = y1;
        vals[l * 6 + 2] = x2; vals[l * 6 + 3] = y2;
        vals[l * 6 + 4] = sc[l]; vals[l * 6 + 5] = (float)cl[l];

        boxes[l] = make_float4(x1, y1, x2, y2);

        bool cand = sc[l] > CONF_TH;
        cands[l] = cand;
        unsigned u = __float_as_uint(sc[l]);
        u = (u & 0x80000000u) ? ~u : (u | 0x80000000u);   // ascending-sortable
        keys[l] = cand
            ? (((unsigned long long)(unsigned)cl[l] << 42)
               | ((unsigned long long)(~u) << 10)
               | (unsigned)p)
            : (0x8000000000000000ull | (unsigned)p);
    }

    // boxes+score+cls to out: 24 contiguous floats = 6 float4 stores
    float4* ob4 = (float4*)(out + ((size_t)n * HW + p0) * 6);
    #pragma unroll
    for (int q = 0; q < 6; q++)
        ob4[q] = make_float4(vals[q * 4 + 0], vals[q * 4 + 1], vals[q * 4 + 2], vals[q * 4 + 3]);

    // keep region: default 0 for every pixel (NMS only writes the kept 1s)
    *(float4*)(out + (size_t)N_IMG * HW * 6 + (size_t)n * HW + p0) =
        make_float4(0.0f, 0.0f, 0.0f, 0.0f);

    // scratch writes (vectorized)
    ulonglong2* kp = (ulonglong2*)&g_key[(size_t)n * HW + p0];
    kp[0] = make_ulonglong2(keys[0], keys[1]);
    kp[1] = make_ulonglong2(keys[2], keys[3]);
    float4* bp = &g_box[(size_t)n * HW + p0];
    #pragma unroll
    for (int l = 0; l < 4; l++) bp[l] = boxes[l];

    // candidate append into per-(image,class) slots
    #pragma unroll
    for (int l = 0; l < 4; l++) {
        if (cands[l]) {
            int task = n * NCLS + cl[l];
            unsigned slot = atomicAdd(&g_cnt[task], 1u);
            if (slot < SLOTS) g_slots[task * SLOTS + slot] = keys[l];
        }
    }
}

// ============================================================
// Kernel B: warp-per-(image,class) NMS. grid = 160, block = 1024.
// ============================================================
__device__ __forceinline__ unsigned long long bitonic_shfl_step(
    unsigned long long key, int j, bool up, int t)
{
    unsigned long long p = __shfl_xor_sync(FULL, key, j);
    bool low     = ((t & j) == 0);
    bool takeMin = (low == up);
    bool swap    = takeMin ? (p < key) : (p > key);
    return swap ? p : key;
}

__global__ __launch_bounds__(1024)
void nms_kernel(float* __restrict__ out)
{
    const int task = blockIdx.x * 32 + (threadIdx.x >> 5);
    if (task >= NTASK) return;
    const int lane = threadIdx.x & 31;
    const int n = task / NCLS;
    const int c = task % NCLS;

    const int m = (int)g_cnt[task];
    __syncwarp(FULL);
    if (lane == 0) g_cnt[task] = 0u;      // restore zero-invariant for next launch
    if (m == 0) return;

    float* keep = out + (size_t)N_IMG * HW * 6 + (size_t)n * HW;
    const float4* boxes = &g_box[(size_t)n * HW];

    if (m <= SLOTS) {
        // ---- fast path: sort ≤32 keys in registers, ballot-greedy ----
        unsigned long long kk = (lane < m) ? g_slots[task * SLOTS + lane] : ~0ull;
        #pragma unroll
        for (int k = 2; k <= 32; k <<= 1) {
            #pragma unroll
            for (int j = k >> 1; j >= 1; j >>= 1)
                kk = bitonic_shfl_step(kk, j, (lane & k) == 0, lane);
        }
        int pos = (int)(kk & 0x3FFu);
        float4 b4 = boxes[pos];            // lane>=m loads pixel 1023 (in-bounds, unused)
        float  ar = (b4.z - b4.x) * (b4.w - b4.y);

        unsigned removed = 0u, keepB = 0u;
        for (int i = 0; i < m; i++) {
            if ((removed >> i) & 1u) continue;     // uniform across warp
            keepB |= 1u << i;
            float wx1 = __shfl_sync(FULL, b4.x, i);
            float wy1 = __shfl_sync(FULL, b4.y, i);
            float wx2 = __shfl_sync(FULL, b4.z, i);
            float wy2 = __shfl_sync(FULL, b4.w, i);
            float wa  = __shfl_sync(FULL, ar,   i);
            float iw = fminf(b4.z, wx2) - fmaxf(b4.x, wx1);
            float ih = fminf(b4.w, wy2) - fmaxf(b4.y, wy1);
            iw = fmaxf(iw, 0.0f);
            ih = fmaxf(ih, 0.0f);
            float inter = iw * ih;
            bool s = (lane > i) && (lane < m) &&
                     (inter > NMS_TH * (ar + wa - inter + 1e-9f));
            removed |= __ballot_sync(FULL, s);
        }
        if (lane < m && ((keepB >> lane) & 1u)) keep[pos] = 1.0f;
    } else {
        // ---- generic fallback (astronomically rare): scan full image keys ----
        const unsigned long long* keys = &g_key[(size_t)n * HW];
        // lane owns pixels p = k*32 + lane, k = 0..31
        unsigned alive = 0u;
        for (int k = 0; k < 32; k++) {
            unsigned long long key = keys[k * 32 + lane];
            bool elig = ((key >> 63) == 0ull) && ((int)((key >> 42) & 0x7Fu) == c);
            if (elig) alive |= 1u << k;
        }
        while (true) {
            unsigned long long bestk = ~0ull;
            for (int k = 0; k < 32; k++)
                if ((alive >> k) & 1u) {
                    unsigned long long key = keys[k * 32 + lane];
                    if (key < bestk) bestk = key;
                }
            #pragma unroll
            for (int d = 16; d >= 1; d >>= 1) {
                unsigned long long o = __shfl_xor_sync(FULL, bestk, d);
                if (o < bestk) bestk = o;
            }
            if (bestk == ~0ull) break;
            int wpos = (int)(bestk & 0x3FFu);
            float4 wb = boxes[wpos];
            float  wa = (wb.z - wb.x) * (wb.w - wb.y);
            if (lane == (wpos & 31)) {
                alive &= ~(1u << (wpos >> 5));
                keep[wpos] = 1.0f;
            }
            for (int k = 0; k < 32; k++)
                if ((alive >> k) & 1u) {
                    int p2 = k * 32 + lane;
                    float4 b2 = boxes[p2];
                    float a2 = (b2.z - b2.x) * (b2.w - b2.y);
                    float iw = fminf(b2.z, wb.z) - fmaxf(b2.x, wb.x);
                    float ih = fminf(b2.w, wb.w) - fmaxf(b2.y, wb.y);
                    iw = fmaxf(iw, 0.0f);
                    ih = fmaxf(ih, 0.0f);
                    float inter = iw * ih;
                    if (inter > NMS_TH * (a2 + wa - inter + 1e-9f))
                        alive &= ~(1u << k);      // suppressed: keep stays 0
                }
            __syncwarp(FULL);
        }
    }
}

extern "C" void kernel_launch(void* const* d_in, const int* in_sizes, int n_in,
                              void* d_out, int out_size)
{
    const float* in = (const float*)d_in[0];
    float* out = (float*)d_out;
    decode_kernel<<<N_IMG * 2, 128>>>(in, out);
    nms_kernel<<<(NTASK + 31) / 32, 1024>>>(out);
}

// round 7
// speedup vs baseline: 1.4195x; 1.4195x over previous
#include <cuda_runtime.h>
#include <math.h>

#define CONF_TH 0.25f
#define NMS_TH  0.35f
#define FULL    0xffffffffu

static constexpr int N_IMG = 64;
static constexpr int HW    = 1024;   // 32*32
static constexpr int NCH   = 85;
static constexpr int NCLS  = 80;
static constexpr int SLOTS = 32;

// dynamic smem layout (bytes):
//  pval  float4[1024] @      0 (16384)   partial argmax values  [q*256+g]
//  pidx  int4  [1024] @  16384 (16384)   partial argmax indices
//  skey  u64   [1024] @  32768 ( 8192)   per-pixel key (fallback path)
//  sslot u64 [80*32]  @  40960 (20480)   per-class candidate slots
//  scnt  u32   [80]   @  61440 (  320)   per-class candidate count
//  keepS u32   [1024] @  61760 ( 4096)   keep flags
//  sbox  float4[1024] @  65856 (16384)   boxes by pixel
static constexpr int SMEM_BYTES = 82240;

__device__ __forceinline__ unsigned long long bitonic_shfl_step(
    unsigned long long key, int j, bool up, int t)
{
    unsigned long long p = __shfl_xor_sync(FULL, key, j);
    bool low     = ((t & j) == 0);
    bool takeMin = (low == up);
    bool swap    = takeMin ? (p < key) : (p > key);
    return swap ? p : key;
}

__global__ __launch_bounds__(1024, 1)
void fastestdet_kernel(const float* __restrict__ in, float* __restrict__ out)
{
    extern __shared__ unsigned char smem_raw[];
    float4*             pval  = (float4*)(smem_raw);
    int4*               pidx  = (int4*)  (smem_raw + 16384);
    unsigned long long* skey  = (unsigned long long*)(smem_raw + 32768);
    unsigned long long* sslot = (unsigned long long*)(smem_raw + 40960);
    unsigned*           scnt  = (unsigned*)(smem_raw + 61440);
    unsigned*           keepS = (unsigned*)(smem_raw + 61760);
    float4*             sbox  = (float4*)(smem_raw + 65856);

    const int n    = blockIdx.x;
    const int t    = threadIdx.x;
    const int lane = t & 31;
    const int wid  = t >> 5;
    const int g    = t & 255;    // pixel group (pixels 4g..4g+3)
    const int q    = t >> 8;     // channel chunk (20 classes each)

    keepS[t] = 0u;
    if (t < NCLS) scnt[t] = 0u;

    // ---------------- decode phase 1: partial argmax over 20 classes ----------------
    const float4* base = (const float4*)(in + (size_t)n * NCH * HW) + g;

    float4 bv = make_float4(-INFINITY, -INFINITY, -INFINITY, -INFINITY);
    int4   bj = make_int4(0, 0, 0, 0);
    const int c0 = q * 20;
    #pragma unroll
    for (int cc = 0; cc < 20; cc++) {
        int c = c0 + cc;
        float4 v = base[(5 + c) * 256];
        if (v.x > bv.x) { bv.x = v.x; bj.x = c; }
        if (v.y > bv.y) { bv.y = v.y; bj.y = c; }
        if (v.z > bv.z) { bv.z = v.z; bj.z = c; }
        if (v.w > bv.w) { bv.w = v.w; bj.w = c; }
    }
    pval[q * 256 + g] = bv;
    pidx[q * 256 + g] = bj;

    // chunk 0 also loads obj + regression channels (kept in registers across the barrier)
    float4 pobj, r0, r1, r2, r3;
    if (q == 0) {
        pobj = base[0 * 256];
        r0   = base[1 * 256];
        r1   = base[2 * 256];
        r2   = base[3 * 256];
        r3   = base[4 * 256];
    }
    __syncthreads();

    // ---------------- decode phase 2: merge + box math (chunk-0 threads) ----------------
    if (q == 0) {
        float4 mv = pval[g];
        int4   mj = pidx[g];
        #pragma unroll
        for (int qq = 1; qq < 4; qq++) {
            float4 v = pval[qq * 256 + g];
            int4   j = pidx[qq * 256 + g];
            if (v.x > mv.x) { mv.x = v.x; mj.x = j.x; }   // strict >: lower chunk wins ties
            if (v.y > mv.y) { mv.y = v.y; mj.y = j.y; }
            if (v.z > mv.z) { mv.z = v.z; mj.z = j.z; }
            if (v.w > mv.w) { mv.w = v.w; mj.w = j.w; }
        }

        float sc[4]  = { pobj.x * mv.x, pobj.y * mv.y, pobj.z * mv.z, pobj.w * mv.w };
        float rr0[4] = { r0.x, r0.y, r0.z, r0.w };
        float rr1[4] = { r1.x, r1.y, r1.z, r1.w };
        float rr2[4] = { r2.x, r2.y, r2.z, r2.w };
        float rr3[4] = { r3.x, r3.y, r3.z, r3.w };
        int   cl[4]  = { mj.x, mj.y, mj.z, mj.w };

        float vals[24];
        #pragma unroll
        for (int l = 0; l < 4; l++) {
            int p = g * 4 + l;
            float gx = (float)(p & 31);
            float gy = (float)(p >> 5);
            float bcx = (tanhf(rr0[l]) + gx) * (1.0f / 32.0f);
            float bcy = (tanhf(rr1[l]) + gy) * (1.0f / 32.0f);
            float bw  = 1.0f / (1.0f + expf(-rr2[l]));
            float bh  = 1.0f / (1.0f + expf(-rr3[l]));
            float x1 = bcx - 0.5f * bw;
            float y1 = bcy - 0.5f * bh;
            float x2 = bcx + 0.5f * bw;
            float y2 = bcy + 0.5f * bh;

            vals[l * 6 + 0] = x1; vals[l * 6 + 1] = y1;
            vals[l * 6 + 2] = x2; vals[l * 6 + 3] = y2;
            vals[l * 6 + 4] = sc[l]; vals[l * 6 + 5] = (float)cl[l];

            sbox[p] = make_float4(x1, y1, x2, y2);

            bool cand = sc[l] > CONF_TH;
            unsigned u = __float_as_uint(sc[l]);
            u = (u & 0x80000000u) ? ~u : (u | 0x80000000u);   // ascending-sortable
            unsigned long long key = cand
                ? (((unsigned long long)(unsigned)cl[l] << 42)
                   | ((unsigned long long)(~u) << 10)
                   | (unsigned)p)
                : (0x8000000000000000ull | (unsigned)p);
            skey[p] = key;
            if (cand) {
                unsigned slot = atomicAdd(&scnt[cl[l]], 1u);
                if (slot < SLOTS) sslot[cl[l] * SLOTS + slot] = key;
            }
        }

        // boxes+score+cls out: 24 contiguous floats = 6 float4 stores
        float4* ob4 = (float4*)(out + ((size_t)n * HW + g * 4) * 6);
        #pragma unroll
        for (int qq = 0; qq < 6; qq++)
            ob4[qq] = make_float4(vals[qq * 4 + 0], vals[qq * 4 + 1],
                                  vals[qq * 4 + 2], vals[qq * 4 + 3]);
    }
    __syncthreads();

    // ---------------- warp-per-class greedy NMS (smem, no barriers) ----------------
    for (int c = wid; c < NCLS; c += 32) {
        int m = (int)scnt[c];
        if (m == 0) continue;

        if (m <= SLOTS) {
            // fast path: sort ≤32 keys in registers, ballot-greedy
            unsigned long long kk = (lane < m) ? sslot[c * SLOTS + lane] : ~0ull;
            #pragma unroll
            for (int k = 2; k <= 32; k <<= 1) {
                #pragma unroll
                for (int j = k >> 1; j >= 1; j >>= 1)
                    kk = bitonic_shfl_step(kk, j, (lane & k) == 0, lane);
            }
            int pos = (int)(kk & 0x3FFu);
            float4 b4 = sbox[pos];                 // lane>=m: pos=1023, in-bounds, unused
            float  ar = (b4.z - b4.x) * (b4.w - b4.y);

            unsigned removed = 0u, keepB = 0u;
            for (int i = 0; i < m; i++) {
                if ((removed >> i) & 1u) continue; // uniform across warp
                keepB |= 1u << i;
                float wx1 = __shfl_sync(FULL, b4.x, i);
                float wy1 = __shfl_sync(FULL, b4.y, i);
                float wx2 = __shfl_sync(FULL, b4.z, i);
                float wy2 = __shfl_sync(FULL, b4.w, i);
                float wa  = __shfl_sync(FULL, ar,   i);
                float iw = fminf(b4.z, wx2) - fmaxf(b4.x, wx1);
                float ih = fminf(b4.w, wy2) - fmaxf(b4.y, wy1);
                iw = fmaxf(iw, 0.0f);
                ih = fmaxf(ih, 0.0f);
                float inter = iw * ih;
                bool s = (lane > i) && (lane < m) &&
                         (inter > NMS_TH * (ar + wa - inter + 1e-9f));
                removed |= __ballot_sync(FULL, s);
            }
            if (lane < m && ((keepB >> lane) & 1u)) keepS[pos] = 1u;
        } else {
            // generic fallback (astronomically rare): scan all pixel keys
            unsigned alive = 0u;            // lane owns pixels k*32+lane
            for (int k = 0; k < 32; k++) {
                unsigned long long key = skey[k * 32 + lane];
                bool elig = ((key >> 63) == 0ull) && ((int)((key >> 42) & 0x7Fu) == c);
                if (elig) alive |= 1u << k;
            }
            while (true) {
                unsigned long long bestk = ~0ull;
                for (int k = 0; k < 32; k++)
                    if ((alive >> k) & 1u) {
                        unsigned long long key = skey[k * 32 + lane];
                        if (key < bestk) bestk = key;
                    }
                #pragma unroll
                for (int d = 16; d >= 1; d >>= 1) {
                    unsigned long long o = __shfl_xor_sync(FULL, bestk, d);
                    if (o < bestk) bestk = o;
                }
                if (bestk == ~0ull) break;
                int wpos = (int)(bestk & 0x3FFu);
                float4 wb = sbox[wpos];
                float  wa = (wb.z - wb.x) * (wb.w - wb.y);
                if (lane == (wpos & 31)) {
                    alive &= ~(1u << (wpos >> 5));
                    keepS[wpos] = 1u;
                }
                for (int k = 0; k < 32; k++)
                    if ((alive >> k) & 1u) {
                        int p2 = k * 32 + lane;
                        float4 b2 = sbox[p2];
                        float a2 = (b2.z - b2.x) * (b2.w - b2.y);
                        float iw = fminf(b2.z, wb.z) - fmaxf(b2.x, wb.x);
                        float ih = fminf(b2.w, wb.w) - fmaxf(b2.y, wb.y);
                        iw = fmaxf(iw, 0.0f);
                        ih = fmaxf(ih, 0.0f);
                        float inter = iw * ih;
                        if (inter > NMS_TH * (a2 + wa - inter + 1e-9f))
                            alive &= ~(1u << k);
                    }
                __syncwarp(FULL);
            }
        }
    }
    __syncthreads();

    // ---------------- keep output (original order) ----------------
    out[(size_t)N_IMG * HW * 6 + (size_t)n * HW + t] = (float)keepS[t];
}

extern "C" void kernel_launch(void* const* d_in, const int* in_sizes, int n_in,
                              void* d_out, int out_size)
{
    const float* in = (const float*)d_in[0];
    float* out = (float*)d_out;
    cudaFuncSetAttribute(fastestdet_kernel,
                         cudaFuncAttributeMaxDynamicSharedMemorySize, SMEM_BYTES);
    fastestdet_kernel<<<N_IMG, 1024, SMEM_BYTES>>>(in, out);
}